// round 1
// baseline (speedup 1.0000x reference)
#include <cuda_runtime.h>
#include <cstdint>
#include <cstddef>

#define NMAX 100000

// ---------------- scratch (device globals; no allocations allowed) ----------
__device__ float g_H[(size_t)NMAX * 64];   // pre-linear out / layer inputs / 32-wide agg3
__device__ float g_G[(size_t)NMAX * 64];   // g = (h@W) * dinv (gather source)
__device__ float g_A[(size_t)NMAX * 64];   // aggregation buffer (atomic target)
__device__ float g_dinv[NMAX];             // deg -> rsqrt(deg)
__device__ int   g_is64;                   // edge_index dtype flag

// ---------------- edge dtype detection --------------------------------------
// int64 little-endian with values < 2^31 => every odd 32-bit word is 0.
// Genuine int32 random indices in [0,1e5): P(64 consecutive odd words == 0) ~ 0.
__global__ void detect_k(const int* __restrict__ ei) {
    int ok = 1;
    for (int i = 0; i < 64; i++) {
        if (ei[2 * i + 1] != 0) { ok = 0; break; }
    }
    g_is64 = ok;
}

__device__ __forceinline__ int load_idx(const int* __restrict__ ei, size_t pos, int is64) {
    return is64 ? ei[2 * pos] : ei[pos];
}

// ---------------- degree / dinv ---------------------------------------------
__global__ void deg_init_k(int n) {
    int i = blockIdx.x * 256 + threadIdx.x;
    if (i < n) g_dinv[i] = 1.0f;            // self-loop contributes 1
}

__global__ void deg_accum_k(const int* __restrict__ ei, int E) {
    int e = blockIdx.x * 256 + threadIdx.x;
    if (e >= E) return;
    int is64 = g_is64;
    int d = load_idx(ei, (size_t)E + (size_t)e, is64);
    atomicAdd(&g_dinv[d], 1.0f);
}

__global__ void dinv_k(int n) {
    int i = blockIdx.x * 256 + threadIdx.x;
    if (i < n) g_dinv[i] = rsqrtf(g_dinv[i]);   // deg >= 1 always
}

// ---------------- GEMM: out = in @ W, fused transforms ----------------------
// Tile: 32 rows x FOUT cols per block, 256 threads (8 threads/row).
// INTR:  input transform  h = relu(raw * dinv[row] + bprev[col])  (prev conv epilogue)
// CONV:  epilogue: v = acc * dinv[row]; write to BOTH outG (gather src) and
//        outA (agg init = self-loop term). Otherwise: v = acc + bout -> outG.
template <int FIN, int FOUT, bool INTR, bool CONV>
__global__ void gemm_k(const float* __restrict__ in, const float* __restrict__ W,
                       const float* __restrict__ bprev, const float* __restrict__ bout,
                       float* __restrict__ outG, float* __restrict__ outA, int n)
{
    constexpr int TILE = 32;
    constexpr int XS   = FIN + 4;                 // pad: bank stride %32 == 4
    constexpr int KC   = (FIN > 64) ? 64 : FIN;   // K-chunk (smem budget)
    __shared__ float Xs[TILE * XS];
    __shared__ float Ws[KC * FOUT];

    const int tid = threadIdx.x;
    const int r0  = blockIdx.x * TILE;

    // --- load X tile (coalesced float4), applying input transform ---
    constexpr int NV = TILE * FIN / 4;
    for (int i = tid; i < NV; i += 256) {
        int r  = i / (FIN / 4);
        int c4 = i % (FIN / 4);
        int row = r0 + r;
        float4 v = make_float4(0.f, 0.f, 0.f, 0.f);
        if (row < n) {
            v = *(const float4*)(in + (size_t)row * FIN + c4 * 4);
            if (INTR) {
                float di = g_dinv[row];
                v.x = fmaxf(v.x * di + bprev[c4 * 4 + 0], 0.f);
                v.y = fmaxf(v.y * di + bprev[c4 * 4 + 1], 0.f);
                v.z = fmaxf(v.z * di + bprev[c4 * 4 + 2], 0.f);
                v.w = fmaxf(v.w * di + bprev[c4 * 4 + 3], 0.f);
            }
        }
        *(float4*)(Xs + r * XS + c4 * 4) = v;
    }

    constexpr int CPT = FOUT / 8;          // cols per thread: 8 (FOUT=64) or 4
    const int r  = tid / 8;
    const int c0 = (tid % 8) * CPT;
    float acc[CPT];
#pragma unroll
    for (int j = 0; j < CPT; j++) acc[j] = 0.f;

    for (int k0 = 0; k0 < FIN; k0 += KC) {
        // load W chunk [KC x FOUT]
        for (int i = tid; i < KC * FOUT / 4; i += 256)
            ((float4*)Ws)[i] = ((const float4*)(W + (size_t)k0 * FOUT))[i];
        __syncthreads();
#pragma unroll 8
        for (int k = 0; k < KC; k++) {
            float a = Xs[r * XS + k0 + k];
#pragma unroll
            for (int j = 0; j < CPT; j++)
                acc[j] += a * Ws[k * FOUT + c0 + j];
        }
        __syncthreads();
    }

    int row = r0 + r;
    if (row < n) {
        float vv[CPT];
        if (CONV) {
            float di = g_dinv[row];
#pragma unroll
            for (int j = 0; j < CPT; j++) vv[j] = acc[j] * di;
        } else {
#pragma unroll
            for (int j = 0; j < CPT; j++) vv[j] = acc[j] + bout[c0 + j];
        }
#pragma unroll
        for (int q = 0; q < CPT / 4; q++) {
            float4 f = make_float4(vv[q*4], vv[q*4+1], vv[q*4+2], vv[q*4+3]);
            *(float4*)(outG + (size_t)row * FOUT + c0 + q * 4) = f;
            if (CONV)
                *(float4*)(outA + (size_t)row * FOUT + c0 + q * 4) = f;
        }
    }
}

// ---------------- edge scatter: A[dst] += G[src] (vector red) ----------------
// VPR float4 per row (16 for 64 cols, 8 for 32 cols); VPR lanes cooperate per edge.
template <int VPR, int SHIFT>
__global__ void scatter_k(const int* __restrict__ ei, const float* __restrict__ G,
                          float* __restrict__ A, int E)
{
    long long t = (long long)blockIdx.x * 256 + threadIdx.x;
    long long total = (long long)E * VPR;
    bool valid = (t < total);
    long long e = t >> SHIFT;
    if (e >= E) e = E - 1;                      // clamp; keep warp converged for shfl
    int c = (int)(t & (VPR - 1));
    int is64 = g_is64;

    int lane = threadIdx.x & 31;
    int s = 0, d = 0;
    if ((lane & (VPR - 1)) == 0) {              // group leader loads indices
        s = load_idx(ei, (size_t)e, is64);
        d = load_idx(ei, (size_t)E + (size_t)e, is64);
    }
    int srcLane = lane & ~(VPR - 1);
    s = __shfl_sync(0xffffffffu, s, srcLane);
    d = __shfl_sync(0xffffffffu, d, srcLane);

    if (valid) {
        float4 v = ((const float4*)G)[(size_t)s * VPR + c];
        float4* p = ((float4*)A) + (size_t)d * VPR + c;
        asm volatile("red.global.add.v4.f32 [%0], {%1, %2, %3, %4};"
                     :: "l"(p), "f"(v.x), "f"(v.y), "f"(v.z), "f"(v.w)
                     : "memory");
    }
}

// ---------------- final: out = L2-normalize(A*dinv + b3) ---------------------
__global__ void final_k(const float* __restrict__ A, const float* __restrict__ b3,
                        float* __restrict__ out, int n)
{
    int row  = blockIdx.x * 8 + (threadIdx.x >> 5);
    int lane = threadIdx.x & 31;
    if (row >= n) return;                       // warp-uniform exit
    float v = A[(size_t)row * 32 + lane] * g_dinv[row] + b3[lane];
    float ss = v * v;
#pragma unroll
    for (int o = 16; o; o >>= 1) ss += __shfl_xor_sync(0xffffffffu, ss, o);
    float nrm = sqrtf(ss);
    out[(size_t)row * 32 + lane] = v / fmaxf(nrm, 1e-12f);
}

// ---------------- launcher ---------------------------------------------------
extern "C" void kernel_launch(void* const* d_in, const int* in_sizes, int n_in,
                              void* d_out, int out_size)
{
    const float* x     = (const float*)d_in[0];
    const int*   ei    = (const int*)  d_in[1];   // int32 or int64 (detected)
    const float* W_pre = (const float*)d_in[2];
    const float* b_pre = (const float*)d_in[3];
    const float* W1    = (const float*)d_in[4];
    const float* b1    = (const float*)d_in[5];
    const float* W2    = (const float*)d_in[6];
    const float* b2    = (const float*)d_in[7];
    const float* W3    = (const float*)d_in[8];
    const float* b3    = (const float*)d_in[9];
    float* out = (float*)d_out;

    const int n = in_sizes[0] / 128;
    const int E = in_sizes[1] / 2;

    float *pH, *pG, *pA;
    cudaGetSymbolAddress((void**)&pH, g_H);
    cudaGetSymbolAddress((void**)&pG, g_G);
    cudaGetSymbolAddress((void**)&pA, g_A);

    const int nb  = (n + 255) / 256;
    const int eb  = (E + 255) / 256;
    const int gb  = (n + 31) / 32;
    const unsigned sb16 = (unsigned)(((long long)E * 16 + 255) / 256);
    const unsigned sb8  = (unsigned)(((long long)E * 8  + 255) / 256);

    detect_k<<<1, 1>>>(ei);
    deg_init_k<<<nb, 256>>>(n);
    deg_accum_k<<<eb, 256>>>(ei, E);
    dinv_k<<<nb, 256>>>(n);

    // pre-linear: H = x @ W_pre + b_pre
    gemm_k<128, 64, false, false><<<gb, 256>>>(x, W_pre, nullptr, b_pre, pH, nullptr, n);

    // conv1: G = (H @ W1)*dinv ; A = G ; A += G[src] over edges
    gemm_k<64, 64, false, true><<<gb, 256>>>(pH, W1, nullptr, nullptr, pG, pA, n);
    scatter_k<16, 4><<<sb16, 256>>>(ei, pG, pA, E);

    // conv2: input = relu(A*dinv + b1) fused into GEMM load (in-place safe per-tile)
    gemm_k<64, 64, true, true><<<gb, 256>>>(pA, W2, b1, nullptr, pG, pA, n);
    scatter_k<16, 4><<<sb16, 256>>>(ei, pG, pA, E);

    // conv3 (64->32): input = relu(A*dinv + b2); agg goes to pH (32-wide)
    gemm_k<64, 32, true, true><<<gb, 256>>>(pA, W3, b2, nullptr, pG, pH, n);
    scatter_k<8, 3><<<sb8, 256>>>(ei, pG, pH, E);

    // out = L2-normalize(pH*dinv + b3)
    final_k<<<(n + 7) / 8, 256>>>(pH, b3, out, n);
}

// round 2
// speedup vs baseline: 2.3138x; 2.3138x over previous
#include <cuda_runtime.h>
#include <cstdint>
#include <cstddef>

#define NMAX 100000
#define EMAX 1700000

// ---------------- scratch (device globals; no allocations allowed) ----------
__device__ float g_H[(size_t)NMAX * 64];
__device__ float g_G[(size_t)NMAX * 64];
__device__ float g_A[(size_t)NMAX * 64];
__device__ float g_dinv[NMAX];
__device__ int   g_deg[NMAX];
__device__ int   g_fill[NMAX];
__device__ int   g_rowptr[NMAX + 1];
__device__ int   g_bsum[1024];
__device__ int   g_csr[EMAX];
__device__ int   g_is64;

// ---------------- edge dtype detection --------------------------------------
// int64 little-endian with values < 2^31 => every odd 32-bit word is 0.
__global__ void detect_k(const int* __restrict__ ei) {
    int ok = 1;
    for (int i = 0; i < 64; i++)
        if (ei[2 * i + 1] != 0) { ok = 0; break; }
    g_is64 = ok;
}

__device__ __forceinline__ int load_idx(const int* __restrict__ ei, size_t pos, int is64) {
    return is64 ? ei[2 * pos] : ei[pos];
}

// ---------------- CSR build --------------------------------------------------
__global__ void zero_k(int n) {
    int i = blockIdx.x * 256 + threadIdx.x;
    if (i < n) { g_deg[i] = 0; g_fill[i] = 0; }
}

__global__ void deg_accum_k(const int* __restrict__ ei, int E) {
    int e = blockIdx.x * 256 + threadIdx.x;
    if (e >= E) return;
    int d = load_idx(ei, (size_t)E + (size_t)e, g_is64);
    atomicAdd(&g_deg[d], 1);
}

// exclusive scan of g_deg into g_rowptr: 3 phases
__global__ void scan1_k(int n) {
    __shared__ int s[256];
    int tx = threadIdx.x;
    int i = blockIdx.x * 256 + tx;
    int v = (i < n) ? g_deg[i] : 0;
    s[tx] = v;
    __syncthreads();
#pragma unroll
    for (int o = 1; o < 256; o <<= 1) {
        int t = 0;
        if (tx >= o) t = s[tx - o];
        __syncthreads();
        if (tx >= o) s[tx] += t;
        __syncthreads();
    }
    if (i < n) g_rowptr[i] = s[tx] - v;      // exclusive within block
    if (tx == 255) g_bsum[blockIdx.x] = s[255];
}

__global__ void scan2_k(int nb) {
    __shared__ int s[512];
    int tx = threadIdx.x;
    int v = (tx < nb) ? g_bsum[tx] : 0;
    s[tx] = v;
    __syncthreads();
#pragma unroll
    for (int o = 1; o < 512; o <<= 1) {
        int t = 0;
        if (tx >= o) t = s[tx - o];
        __syncthreads();
        if (tx >= o) s[tx] += t;
        __syncthreads();
    }
    if (tx < nb) g_bsum[tx] = s[tx] - v;     // exclusive block offsets
}

__global__ void scan3_k(int n, int E) {
    int i = blockIdx.x * 256 + threadIdx.x;
    if (i < n) {
        g_rowptr[i] += g_bsum[i >> 8];
        g_dinv[i] = rsqrtf((float)(g_deg[i] + 1));   // +1: self-loop
    }
    if (i == 0) g_rowptr[n] = E;
}

__global__ void fill_k(const int* __restrict__ ei, int E) {
    int e = blockIdx.x * 256 + threadIdx.x;
    if (e >= E) return;
    int is64 = g_is64;
    int s = load_idx(ei, (size_t)e, is64);
    int d = load_idx(ei, (size_t)E + (size_t)e, is64);
    int pos = g_rowptr[d] + atomicAdd(&g_fill[d], 1);
    g_csr[pos] = s;
}

// ---------------- GEMM: out = f(in) @ W, fused transforms -------------------
// 64x FOUT tile, 256 threads, 4x(FOUT/16) register blocking, K chunked at 64.
// INTR: input transform h = relu(raw * dinv[row] + bprev[col]) (prev conv epilogue)
// CONV: epilogue v = acc * dinv[row]  (gather source);  else v = acc + bout.
template <int FIN, int FOUT, bool INTR, bool CONV>
__global__ void gemm_k(const float* __restrict__ in, const float* __restrict__ W,
                       const float* __restrict__ bprev, const float* __restrict__ bout,
                       float* __restrict__ out, int n)
{
    constexpr int TILE = 64;
    constexpr int KC   = (FIN > 64) ? 64 : FIN;
    constexpr int XS   = KC + 4;
    constexpr int TN   = FOUT / 16;           // 4 (FOUT=64) or 2 (FOUT=32)
    __shared__ float Xs[TILE * XS];
    __shared__ float Ws[KC * FOUT];

    const int tid = threadIdx.x;
    const int r0b = blockIdx.x * TILE;
    const int tx = tid & 15, ty = tid >> 4;
    const int r0 = ty * 4, c0 = tx * TN;

    float acc[4][TN];
#pragma unroll
    for (int i = 0; i < 4; i++)
#pragma unroll
        for (int j = 0; j < TN; j++) acc[i][j] = 0.f;

    for (int k0 = 0; k0 < FIN; k0 += KC) {
        // load X tile chunk [TILE x KC] with optional input transform
        constexpr int NV = TILE * KC / 4;
        for (int i = tid; i < NV; i += 256) {
            int r = i / (KC / 4);
            int c4 = i % (KC / 4);
            int row = r0b + r;
            int col = k0 + c4 * 4;
            float4 v = make_float4(0.f, 0.f, 0.f, 0.f);
            if (row < n) {
                v = *(const float4*)(in + (size_t)row * FIN + col);
                if (INTR) {
                    float di = g_dinv[row];
                    v.x = fmaxf(fmaf(v.x, di, bprev[col + 0]), 0.f);
                    v.y = fmaxf(fmaf(v.y, di, bprev[col + 1]), 0.f);
                    v.z = fmaxf(fmaf(v.z, di, bprev[col + 2]), 0.f);
                    v.w = fmaxf(fmaf(v.w, di, bprev[col + 3]), 0.f);
                }
            }
            *(float4*)(Xs + r * XS + c4 * 4) = v;
        }
        // load W chunk [KC x FOUT]
        for (int i = tid; i < KC * FOUT / 4; i += 256)
            ((float4*)Ws)[i] = ((const float4*)(W + (size_t)k0 * FOUT))[i];
        __syncthreads();

#pragma unroll 4
        for (int k = 0; k < KC; k++) {
            float x0 = Xs[(r0 + 0) * XS + k];
            float x1 = Xs[(r0 + 1) * XS + k];
            float x2 = Xs[(r0 + 2) * XS + k];
            float x3 = Xs[(r0 + 3) * XS + k];
#pragma unroll
            for (int j = 0; j < TN; j++) {
                float w = Ws[k * FOUT + c0 + j];
                acc[0][j] = fmaf(x0, w, acc[0][j]);
                acc[1][j] = fmaf(x1, w, acc[1][j]);
                acc[2][j] = fmaf(x2, w, acc[2][j]);
                acc[3][j] = fmaf(x3, w, acc[3][j]);
            }
        }
        __syncthreads();
    }

#pragma unroll
    for (int i = 0; i < 4; i++) {
        int row = r0b + r0 + i;
        if (row < n) {
            if (CONV) {
                float di = g_dinv[row];
#pragma unroll
                for (int j = 0; j < TN; j++)
                    out[(size_t)row * FOUT + c0 + j] = acc[i][j] * di;
            } else {
#pragma unroll
                for (int j = 0; j < TN; j++)
                    out[(size_t)row * FOUT + c0 + j] = acc[i][j] + bout[c0 + j];
            }
        }
    }
}

// ---------------- gather: A[dst] = G[dst] + sum_{src in CSR[dst]} G[src] ----
// One warp per destination row. COLS = 64 (2 floats/lane) or 32 (1 float/lane).
template <int COLS>
__global__ void gather_k(const float* __restrict__ G, float* __restrict__ A, int n)
{
    int row  = blockIdx.x * 8 + (threadIdx.x >> 5);
    int lane = threadIdx.x & 31;
    if (row >= n) return;                         // warp-uniform exit
    int beg = g_rowptr[row], end = g_rowptr[row + 1];
    float a0 = G[(size_t)row * COLS + lane];      // self-loop term
    float a1 = 0.f;
    if (COLS == 64) a1 = G[(size_t)row * COLS + 32 + lane];
    for (int p = beg; p < end; p += 32) {
        int m = end - p;
        if (m > 32) m = 32;
        int id = (lane < m) ? g_csr[p + lane] : 0;
#pragma unroll 4
        for (int j = 0; j < m; j++) {
            int s = __shfl_sync(0xffffffffu, id, j);
            a0 += G[(size_t)s * COLS + lane];
            if (COLS == 64) a1 += G[(size_t)s * COLS + 32 + lane];
        }
    }
    A[(size_t)row * COLS + lane] = a0;
    if (COLS == 64) A[(size_t)row * COLS + 32 + lane] = a1;
}

// ---------------- final: out = L2-normalize(A*dinv + b3) ---------------------
__global__ void final_k(const float* __restrict__ A, const float* __restrict__ b3,
                        float* __restrict__ out, int n)
{
    int row  = blockIdx.x * 8 + (threadIdx.x >> 5);
    int lane = threadIdx.x & 31;
    if (row >= n) return;
    float v = A[(size_t)row * 32 + lane] * g_dinv[row] + b3[lane];
    float ss = v * v;
#pragma unroll
    for (int o = 16; o; o >>= 1) ss += __shfl_xor_sync(0xffffffffu, ss, o);
    float nrm = sqrtf(ss);
    out[(size_t)row * 32 + lane] = v / fmaxf(nrm, 1e-12f);
}

// ---------------- launcher ---------------------------------------------------
extern "C" void kernel_launch(void* const* d_in, const int* in_sizes, int n_in,
                              void* d_out, int out_size)
{
    const float* x     = (const float*)d_in[0];
    const int*   ei    = (const int*)  d_in[1];
    const float* W_pre = (const float*)d_in[2];
    const float* b_pre = (const float*)d_in[3];
    const float* W1    = (const float*)d_in[4];
    const float* b1    = (const float*)d_in[5];
    const float* W2    = (const float*)d_in[6];
    const float* b2    = (const float*)d_in[7];
    const float* W3    = (const float*)d_in[8];
    const float* b3    = (const float*)d_in[9];
    float* out = (float*)d_out;

    const int n = in_sizes[0] / 128;
    const int E = in_sizes[1] / 2;

    float *pH, *pG, *pA;
    cudaGetSymbolAddress((void**)&pH, g_H);
    cudaGetSymbolAddress((void**)&pG, g_G);
    cudaGetSymbolAddress((void**)&pA, g_A);

    const int nb = (n + 255) / 256;
    const int eb = (E + 255) / 256;
    const int gb = (n + 63) / 64;
    const int wb = (n + 7) / 8;

    // ---- CSR build (once per launch; reused by all 3 convs) ----
    detect_k<<<1, 1>>>(ei);
    zero_k<<<nb, 256>>>(n);
    deg_accum_k<<<eb, 256>>>(ei, E);
    scan1_k<<<nb, 256>>>(n);
    scan2_k<<<1, 512>>>(nb);
    scan3_k<<<nb, 256>>>(n, E);
    fill_k<<<eb, 256>>>(ei, E);

    // ---- network ----
    // pre-linear: H = x @ W_pre + b_pre
    gemm_k<128, 64, false, false><<<gb, 256>>>(x, W_pre, nullptr, b_pre, pH, n);

    // conv1: G = (H @ W1)*dinv ; A = G[row] + sum G[src]
    gemm_k<64, 64, false, true><<<gb, 256>>>(pH, W1, nullptr, nullptr, pG, n);
    gather_k<64><<<wb, 256>>>(pG, pA, n);

    // conv2: in = relu(A*dinv + b1) fused into GEMM load
    gemm_k<64, 64, true, true><<<gb, 256>>>(pA, W2, b1, nullptr, pG, n);
    gather_k<64><<<wb, 256>>>(pG, pA, n);

    // conv3 (64->32)
    gemm_k<64, 32, true, true><<<gb, 256>>>(pA, W3, b2, nullptr, pG, n);
    gather_k<32><<<wb, 256>>>(pG, pA, n);

    // out = L2-normalize(A*dinv + b3)
    final_k<<<wb, 256>>>(pA, b3, out, n);
}

// round 3
// speedup vs baseline: 2.4857x; 1.0743x over previous
#include <cuda_runtime.h>
#include <cstdint>
#include <cstddef>

#define NMAX 100000
#define EMAX 1700000

// ---------------- scratch (device globals; no allocations allowed) ----------
__device__ float g_H[(size_t)NMAX * 64];
__device__ float g_G[(size_t)NMAX * 64];
__device__ float g_A[(size_t)NMAX * 64];
__device__ float g_dinv[NMAX];
__device__ int   g_deg[NMAX];
__device__ int   g_fill[NMAX];
__device__ int   g_rowptr[NMAX + 1];
__device__ int   g_bsum[1024];
__device__ int   g_csr[EMAX];
__device__ int   g_is64;

typedef unsigned long long ull;

// f32x2 packed FMA (sm_100+): d = a*b + c, lanewise on 2 packed fp32
__device__ __forceinline__ void fma2(ull& d, ull a, ull b) {
    asm("fma.rn.f32x2 %0, %1, %2, %0;" : "+l"(d) : "l"(a), "l"(b));
}
__device__ __forceinline__ ull dup2(float x) {
    ull r;
    asm("mov.b64 %0, {%1, %1};" : "=l"(r) : "f"(x));
    return r;
}
__device__ __forceinline__ float2 unpk(ull a) {
    float2 v;
    asm("mov.b64 {%0, %1}, %2;" : "=f"(v.x), "=f"(v.y) : "l"(a));
    return v;
}

// ---------------- zero + edge dtype detection --------------------------------
__global__ void zero_k(const int* __restrict__ ei, int n) {
    int i = blockIdx.x * 256 + threadIdx.x;
    if (i < n) { g_deg[i] = 0; g_fill[i] = 0; }
    if (blockIdx.x == 0 && threadIdx.x == 0) {
        // int64 little-endian, values < 2^31 => odd 32-bit words all zero
        int ok = 1;
        for (int j = 0; j < 64; j++)
            if (ei[2 * j + 1] != 0) { ok = 0; break; }
        g_is64 = ok;
    }
}

// ---------------- CSR build --------------------------------------------------
__global__ void deg_accum_k(const int* __restrict__ ei, int E) {
    int e = blockIdx.x * 256 + threadIdx.x;
    if (e >= E) return;
    int d;
    if (g_is64) d = ((const int2*)ei)[(size_t)E + e].x;
    else        d = ei[(size_t)E + e];
    atomicAdd(&g_deg[d], 1);
}

__global__ void scan1_k(int n) {
    __shared__ int s[256];
    int tx = threadIdx.x;
    int i = blockIdx.x * 256 + tx;
    int v = (i < n) ? g_deg[i] : 0;
    s[tx] = v;
    __syncthreads();
#pragma unroll
    for (int o = 1; o < 256; o <<= 1) {
        int t = 0;
        if (tx >= o) t = s[tx - o];
        __syncthreads();
        if (tx >= o) s[tx] += t;
        __syncthreads();
    }
    if (i < n) g_rowptr[i] = s[tx] - v;
    if (tx == 255) g_bsum[blockIdx.x] = s[255];
}

__global__ void scan2_k(int nb) {
    __shared__ int s[512];
    int tx = threadIdx.x;
    int v = (tx < nb) ? g_bsum[tx] : 0;
    s[tx] = v;
    __syncthreads();
#pragma unroll
    for (int o = 1; o < 512; o <<= 1) {
        int t = 0;
        if (tx >= o) t = s[tx - o];
        __syncthreads();
        if (tx >= o) s[tx] += t;
        __syncthreads();
    }
    if (tx < nb) g_bsum[tx] = s[tx] - v;
}

__global__ void scan3_k(int n, int E) {
    int i = blockIdx.x * 256 + threadIdx.x;
    if (i < n) {
        g_rowptr[i] += g_bsum[i >> 8];
        g_dinv[i] = rsqrtf((float)(g_deg[i] + 1));
    }
    if (i == 0) g_rowptr[n] = E;
}

__global__ void fill_k(const int* __restrict__ ei, int E) {
    int e = blockIdx.x * 256 + threadIdx.x;
    if (e >= E) return;
    int s, d;
    if (g_is64) {
        s = ((const int2*)ei)[e].x;
        d = ((const int2*)ei)[(size_t)E + e].x;
    } else {
        s = ei[e];
        d = ei[(size_t)E + e];
    }
    int pos = g_rowptr[d] + atomicAdd(&g_fill[d], 1);
    g_csr[pos] = s;
}

// ---------------- GEMM with f32x2 packed FMA ---------------------------------
// 128 threads/block, thread computes 8 rows x 8 cols (4 f32x2 col-pairs).
// CG = FOUT/8 col-groups, RG = 128/CG row-groups, ROWS = RG*8 rows/tile.
// K chunked at 32. X tile in smem, XOR-swizzled float4 blocks for bank freedom.
// INTR: input transform h = relu(raw*dinv[row] + bprev[col]).
// CONV: epilogue v = acc*dinv[row]; else v = acc + bout[col].
template <int FIN, int FOUT, bool INTR, bool CONV>
__global__ void __launch_bounds__(128) gemm_k(
    const float* __restrict__ in, const float* __restrict__ W,
    const float* __restrict__ bprev, const float* __restrict__ bout,
    float* __restrict__ out, int n)
{
    constexpr int CG   = FOUT / 8;
    constexpr int RG   = 128 / CG;
    constexpr int ROWS = RG * 8;
    constexpr int KC   = 32;
    constexpr int XS   = KC + 4;          // floats per row (36)
    constexpr int NC4  = KC / 4;          // float4 blocks per row (8)

    __shared__ float Xs[ROWS * XS];
    __shared__ float Ws[KC * FOUT];

    const int tid = threadIdx.x;
    const int r0b = blockIdx.x * ROWS;
    const int rg  = tid / CG;
    const int cg  = tid % CG;
    const int r0  = rg * 8;
    const int c0  = cg * 8;

    ull acc[8][4];
#pragma unroll
    for (int i = 0; i < 8; i++)
#pragma unroll
        for (int j = 0; j < 4; j++) acc[i][j] = 0ull;

    for (int k0 = 0; k0 < FIN; k0 += KC) {
        // ---- load X tile chunk [ROWS x KC], swizzled float4 stores ----
        constexpr int NV = ROWS * NC4;     // float4 count
        for (int idx = tid; idx < NV; idx += 128) {
            int r  = idx / NC4;
            int c4 = idx % NC4;
            int row = r0b + r;
            int col = k0 + c4 * 4;
            float4 v = make_float4(0.f, 0.f, 0.f, 0.f);
            if (row < n) {
                v = *(const float4*)(in + (size_t)row * FIN + col);
                if (INTR) {
                    float di = g_dinv[row];
                    v.x = fmaxf(fmaf(v.x, di, bprev[col + 0]), 0.f);
                    v.y = fmaxf(fmaf(v.y, di, bprev[col + 1]), 0.f);
                    v.z = fmaxf(fmaf(v.z, di, bprev[col + 2]), 0.f);
                    v.w = fmaxf(fmaf(v.w, di, bprev[col + 3]), 0.f);
                }
            }
            int sc4 = c4 ^ ((r >> 3) & (NC4 - 1));
            *(float4*)(Xs + r * XS + sc4 * 4) = v;
        }
        // ---- load W chunk [KC x FOUT] ----
        for (int idx = tid; idx < KC * FOUT / 4; idx += 128)
            ((float4*)Ws)[idx] = ((const float4*)(W + (size_t)k0 * FOUT))[idx];
        __syncthreads();

        // ---- inner loop: 4 k per step ----
#pragma unroll
        for (int kk = 0; kk < KC; kk += 4) {
            float4 xv[8];
#pragma unroll
            for (int i = 0; i < 8; i++) {
                int r  = r0 + i;
                int sc = (kk >> 2) ^ ((r >> 3) & (NC4 - 1));
                xv[i] = *(const float4*)(Xs + r * XS + sc * 4);
            }
#pragma unroll
            for (int kj = 0; kj < 4; kj++) {
                const float* wr = Ws + (kk + kj) * FOUT + c0;
                ulonglong2 wA = *(const ulonglong2*)(wr);
                ulonglong2 wB = *(const ulonglong2*)(wr + 4);
#pragma unroll
                for (int i = 0; i < 8; i++) {
                    float xs = (kj == 0) ? xv[i].x : (kj == 1) ? xv[i].y
                             : (kj == 2) ? xv[i].z : xv[i].w;
                    ull xd = dup2(xs);
                    fma2(acc[i][0], xd, wA.x);
                    fma2(acc[i][1], xd, wA.y);
                    fma2(acc[i][2], xd, wB.x);
                    fma2(acc[i][3], xd, wB.y);
                }
            }
        }
        __syncthreads();
    }

    // ---- epilogue ----
#pragma unroll
    for (int i = 0; i < 8; i++) {
        int row = r0b + r0 + i;
        if (row < n) {
            float v[8];
#pragma unroll
            for (int j = 0; j < 4; j++) {
                float2 p = unpk(acc[i][j]);
                v[2 * j] = p.x; v[2 * j + 1] = p.y;
            }
            if (CONV) {
                float di = g_dinv[row];
#pragma unroll
                for (int j = 0; j < 8; j++) v[j] *= di;
            } else {
#pragma unroll
                for (int j = 0; j < 8; j++) v[j] += bout[c0 + j];
            }
            float* o = out + (size_t)row * FOUT + c0;
            *(float4*)(o)     = make_float4(v[0], v[1], v[2], v[3]);
            *(float4*)(o + 4) = make_float4(v[4], v[5], v[6], v[7]);
        }
    }
}

// ---------------- gather (64 cols): A[dst] = G[dst] + sum G[src] -------------
__global__ void gather64_k(const float* __restrict__ G, float* __restrict__ A, int n)
{
    int row  = blockIdx.x * 8 + (threadIdx.x >> 5);
    int lane = threadIdx.x & 31;
    if (row >= n) return;                        // warp-uniform exit
    const float2* G2 = (const float2*)G;
    int beg = g_rowptr[row], end = g_rowptr[row + 1];
    float2 a = G2[(size_t)row * 32 + lane];      // self-loop term
    for (int p = beg; p < end; p += 32) {
        int m = end - p;
        if (m > 32) m = 32;
        int id = (lane < m) ? g_csr[p + lane] : 0;
#pragma unroll 4
        for (int j = 0; j < m; j++) {
            int s = __shfl_sync(0xffffffffu, id, j);
            float2 v = G2[(size_t)s * 32 + lane];
            a.x += v.x; a.y += v.y;
        }
    }
    ((float2*)A)[(size_t)row * 32 + lane] = a;
}

// ---------------- fused gather (32 cols) + L2 normalize ----------------------
__global__ void gather_final_k(const float* __restrict__ G, const float* __restrict__ b3,
                               float* __restrict__ out, int n)
{
    int row  = blockIdx.x * 8 + (threadIdx.x >> 5);
    int lane = threadIdx.x & 31;
    if (row >= n) return;
    int beg = g_rowptr[row], end = g_rowptr[row + 1];
    float a = G[(size_t)row * 32 + lane];
    for (int p = beg; p < end; p += 32) {
        int m = end - p;
        if (m > 32) m = 32;
        int id = (lane < m) ? g_csr[p + lane] : 0;
#pragma unroll 4
        for (int j = 0; j < m; j++) {
            int s = __shfl_sync(0xffffffffu, id, j);
            a += G[(size_t)s * 32 + lane];
        }
    }
    float v = a * g_dinv[row] + b3[lane];
    float ss = v * v;
#pragma unroll
    for (int o = 16; o; o >>= 1) ss += __shfl_xor_sync(0xffffffffu, ss, o);
    float nrm = sqrtf(ss);
    out[(size_t)row * 32 + lane] = v / fmaxf(nrm, 1e-12f);
}

// ---------------- launcher ---------------------------------------------------
extern "C" void kernel_launch(void* const* d_in, const int* in_sizes, int n_in,
                              void* d_out, int out_size)
{
    const float* x     = (const float*)d_in[0];
    const int*   ei    = (const int*)  d_in[1];
    const float* W_pre = (const float*)d_in[2];
    const float* b_pre = (const float*)d_in[3];
    const float* W1    = (const float*)d_in[4];
    const float* b1    = (const float*)d_in[5];
    const float* W2    = (const float*)d_in[6];
    const float* b2    = (const float*)d_in[7];
    const float* W3    = (const float*)d_in[8];
    const float* b3    = (const float*)d_in[9];
    float* out = (float*)d_out;

    const int n = in_sizes[0] / 128;
    const int E = in_sizes[1] / 2;

    float *pH, *pG, *pA;
    cudaGetSymbolAddress((void**)&pH, g_H);
    cudaGetSymbolAddress((void**)&pG, g_G);
    cudaGetSymbolAddress((void**)&pA, g_A);

    const int nb  = (n + 255) / 256;
    const int eb  = (E + 255) / 256;
    const int g64 = (n + 127) / 128;   // ROWS=128 for FOUT=64
    const int g32 = (n + 255) / 256;   // ROWS=256 for FOUT=32
    const int wb  = (n + 7) / 8;

    // ---- CSR build (reused by all 3 convs) ----
    zero_k<<<nb, 256>>>(ei, n);
    deg_accum_k<<<eb, 256>>>(ei, E);
    scan1_k<<<nb, 256>>>(n);
    scan2_k<<<1, 512>>>(nb);
    scan3_k<<<nb, 256>>>(n, E);
    fill_k<<<eb, 256>>>(ei, E);

    // ---- network ----
    gemm_k<128, 64, false, false><<<g64, 128>>>(x, W_pre, nullptr, b_pre, pH, n);

    gemm_k<64, 64, false, true><<<g64, 128>>>(pH, W1, nullptr, nullptr, pG, n);
    gather64_k<<<wb, 256>>>(pG, pA, n);

    gemm_k<64, 64, true, true><<<g64, 128>>>(pA, W2, b1, nullptr, pG, n);
    gather64_k<<<wb, 256>>>(pG, pA, n);

    gemm_k<64, 32, true, true><<<g32, 128>>>(pA, W3, b2, nullptr, pG, n);
    gather_final_k<<<wb, 256>>>(pG, b3, out, n);
}